// round 5
// baseline (speedup 1.0000x reference)
#include <cuda_runtime.h>
#include <cuda_fp16.h>

#define NN   100000
#define EE   1600000
#define GG   100
#define HH   128
#define OUTF 10
#define CAP  128

typedef unsigned long long u64;

// ---------- device scratch ----------
__device__ __half g_bufA[(size_t)NN * HH];  // hs0 = dis*(x@W1), fp16
__device__ float  g_bufC[(size_t)NN * HH];  // h1 = relu(agg1), fp32
__device__ __half g_bufB[(size_t)NN * HH];  // zs = dis*(h1@W2), fp16
__device__ int    g_pad[(size_t)NN * CAP];
__device__ int    g_cur[NN];
__device__ float  g_dis[NN];
__device__ float  g_pooled[GG * HH];
__device__ float  g_gcnt[GG];

// ---------- f32x2 helpers (for gemm2) ----------
__device__ __forceinline__ u64 fma2(u64 a, u64 b, u64 c) {
    u64 d;
    asm("fma.rn.f32x2 %0, %1, %2, %3;" : "=l"(d) : "l"(a), "l"(b), "l"(c));
    return d;
}
__device__ __forceinline__ u64 splat2(float f) {
    u64 d; unsigned u = __float_as_uint(f);
    asm("mov.b64 %0, {%1, %1};" : "=l"(d) : "r"(u));
    return d;
}
__device__ __forceinline__ void unpack2(u64 v, float& lo, float& hi) {
    unsigned a, b;
    asm("mov.b64 {%0, %1}, %2;" : "=r"(a), "=r"(b) : "l"(v));
    lo = __uint_as_float(a); hi = __uint_as_float(b);
}

__device__ __forceinline__ uint2 pack_h4(float4 o) {
    __half2 lo = __floats2half2_rn(o.x, o.y);
    __half2 hi = __floats2half2_rn(o.z, o.w);
    uint2 r;
    r.x = *(unsigned*)&lo;
    r.y = *(unsigned*)&hi;
    return r;
}

// ---------- hp gather primitives ----------
// One lane owns 8 features (uint4 of 4 half2). fp16 accumulate, fp32 flush.
__device__ __forceinline__ void add_row(__half2 h[4], const uint4* __restrict__ A,
                                        int row, int fl) {
    uint4 v = __ldg(&A[(size_t)row * 16 + fl]);
    h[0] = __hadd2(h[0], *(__half2*)&v.x);
    h[1] = __hadd2(h[1], *(__half2*)&v.y);
    h[2] = __hadd2(h[2], *(__half2*)&v.z);
    h[3] = __hadd2(h[3], *(__half2*)&v.w);
}
__device__ __forceinline__ void flush(__half2 h[4], float fa[8]) {
#pragma unroll
    for (int j = 0; j < 4; j++) {
        float2 f = __half22float2(h[j]);
        fa[2 * j]     += f.x;
        fa[2 * j + 1] += f.y;
        h[j] = __float2half2_rn(0.f);
    }
}

// Gather sum of fp16 rows of all in-edges + self row of node n.
// lanes 0-15 (L) and 16-31 (H) split the edge stream; results must be
// combined across half-warps afterwards. fa[8] = this lane's partial.
__device__ __forceinline__ void gather_node(const __half* __restrict__ buf,
                                            int n, int lane, float fa[8]) {
    int grp = lane >> 4, fl = lane & 15;
    int cnt = g_cur[n]; if (cnt > CAP) cnt = CAP;
    const int* lst = g_pad + (size_t)n * CAP;
    const uint4* A = (const uint4*)buf;       // row = 16 uint4

#pragma unroll
    for (int j = 0; j < 8; j++) fa[j] = 0.f;
    __half2 hacc[4];
#pragma unroll
    for (int j = 0; j < 4; j++) hacc[j] = __float2half2_rn(0.f);

    int k = 0, sf = 0;
    // 8-edge chunks: L handles lst[k..k+3], H handles lst[k+4..k+7]
    for (; k + 8 <= cnt; k += 8) {
        int4 s4 = *(const int4*)&lst[k + grp * 4];
        add_row(hacc, A, s4.x, fl);
        add_row(hacc, A, s4.y, fl);
        add_row(hacc, A, s4.z, fl);
        add_row(hacc, A, s4.w, fl);
        if (++sf == 2) { flush(hacc, fa); sf = 0; }   // <=8 fp16 adds per partial
    }
    // remainder pairs
    for (; k + 2 <= cnt; k += 2)
        add_row(hacc, A, __ldg(&lst[k + grp]), fl);
    // tail: L adds self row; H adds last odd edge (if any)
    if (grp == 0) {
        add_row(hacc, A, n, fl);
    } else if (k < cnt) {
        add_row(hacc, A, __ldg(&lst[k]), fl);
    }
    flush(hacc, fa);
}

__device__ __forceinline__ void combine_halves(float fa[8]) {
#pragma unroll
    for (int j = 0; j < 8; j++)
        fa[j] += __shfl_down_sync(0xffffffffu, fa[j], 16);
}

// ---------- kernels ----------
__global__ void k_zero() {
    int i = blockIdx.x * blockDim.x + threadIdx.x;
    if (i < NN) g_cur[i] = 0;
    if (i < GG * HH) g_pooled[i] = 0.f;
    if (i < GG) g_gcnt[i] = 0.f;
}

__global__ void k_fill(const int* __restrict__ src, const int* __restrict__ dst) {
    int e = blockIdx.x * blockDim.x + threadIdx.x;
    if (e < EE) {
        int d = dst[e];
        int p = atomicAdd(&g_cur[d], 1);
        if (p < CAP) g_pad[(size_t)d * CAP + p] = src[e];
    }
}

// hs0 = dis_n * (x_n @ W1) -> fp16; publishes g_dis. Warp per node.
__global__ void __launch_bounds__(256) k_gemm_in(const float* __restrict__ x,
                                                 const float* __restrict__ W1) {
    int gid = blockIdx.x * blockDim.x + threadIdx.x;
    int n = gid >> 5, lane = gid & 31;
    if (n >= NN) return;
    float dis = rsqrtf((float)(g_cur[n] + 1));
    if (lane == 0) g_dis[n] = dis;
    float x0 = x[n * 3 + 0], x1 = x[n * 3 + 1], x2 = x[n * 3 + 2];
    const float4* W = ((const float4*)W1) + lane;
    float4 w0 = W[0], w1 = W[32], w2 = W[64];
    float4 o;
    o.x = dis * fmaf(x0, w0.x, fmaf(x1, w1.x, x2 * w2.x));
    o.y = dis * fmaf(x0, w0.y, fmaf(x1, w1.y, x2 * w2.y));
    o.z = dis * fmaf(x0, w0.z, fmaf(x1, w1.z, x2 * w2.z));
    o.w = dis * fmaf(x0, w0.w, fmaf(x1, w1.w, x2 * w2.w));
    ((uint2*)(g_bufA + (size_t)n * HH))[lane] = pack_h4(o);
}

// Layer-1 aggregate + bias + relu -> h1 (fp32). Warp per node, paired lanes.
__global__ void __launch_bounds__(256) k_agg1(const float* __restrict__ b1) {
    int gid = blockIdx.x * blockDim.x + threadIdx.x;
    int n = gid >> 5, lane = gid & 31;
    if (n >= NN) return;
    float fa[8];
    gather_node(g_bufA, n, lane, fa);
    combine_halves(fa);
    if (lane < 16) {
        int fl = lane;
        float dis = g_dis[n];
        float* row = g_bufC + (size_t)n * HH + fl * 8;
        const float* bb = b1 + fl * 8;
        float4 o0, o1;
        o0.x = fmaxf(fmaf(fa[0], dis, bb[0]), 0.f);
        o0.y = fmaxf(fmaf(fa[1], dis, bb[1]), 0.f);
        o0.z = fmaxf(fmaf(fa[2], dis, bb[2]), 0.f);
        o0.w = fmaxf(fmaf(fa[3], dis, bb[3]), 0.f);
        o1.x = fmaxf(fmaf(fa[4], dis, bb[4]), 0.f);
        o1.y = fmaxf(fmaf(fa[5], dis, bb[5]), 0.f);
        o1.z = fmaxf(fmaf(fa[6], dis, bb[6]), 0.f);
        o1.w = fmaxf(fmaf(fa[7], dis, bb[7]), 0.f);
        ((float4*)row)[0] = o0;
        ((float4*)row)[1] = o1;
    }
}

// zs = dis * (h1 @ W2) -> fp16.  64 nodes/block, warp = 8 nodes x 4 cols, f32x2.
__global__ void __launch_bounds__(256) k_gemm2(const float* __restrict__ W2) {
    __shared__ float hs[64][HH];
    int nb0 = blockIdx.x * 64;
    int t = threadIdx.x;

    for (int i = t; i < 64 * 32; i += 256) {
        int r = i >> 5, c4 = i & 31;
        int node = nb0 + r; if (node >= NN) node = NN - 1;
        ((float4*)hs[r])[c4] = ((const float4*)(g_bufC + (size_t)node * HH))[c4];
    }
    __syncthreads();

    int w = t >> 5, lane = t & 31;
    int nb = w * 8;

    u64 acc[8][2];
#pragma unroll
    for (int p = 0; p < 8; p++) { acc[p][0] = 0ull; acc[p][1] = 0ull; }

    const float4* Wr = (const float4*)W2;
#pragma unroll 2
    for (int k = 0; k < HH; k++) {
        float4 wv = __ldg(&Wr[k * 32 + lane]);
        u64 wb0 = ((const u64*)&wv)[0];
        u64 wb1 = ((const u64*)&wv)[1];
#pragma unroll
        for (int p = 0; p < 8; p++) {
            u64 ha = splat2(hs[nb + p][k]);
            acc[p][0] = fma2(ha, wb0, acc[p][0]);
            acc[p][1] = fma2(ha, wb1, acc[p][1]);
        }
    }

#pragma unroll
    for (int p = 0; p < 8; p++) {
        int node = nb0 + nb + p;
        if (node >= NN) break;
        float dis = g_dis[node];
        float4 o;
        unpack2(acc[p][0], o.x, o.y);
        unpack2(acc[p][1], o.z, o.w);
        o.x *= dis; o.y *= dis; o.z *= dis; o.w *= dis;
        ((uint2*)(g_bufB + (size_t)node * HH))[lane] = pack_h4(o);
    }
}

// Layer-2 aggregate + relu + fused mean-pool (block smem reduction).
__global__ void __launch_bounds__(256) k_agg_pool(const float* __restrict__ b2,
                                                   const int* __restrict__ batch) {
    __shared__ float acc[HH];
    __shared__ float scnt;
    __shared__ int g0s;
    int tid = threadIdx.x;
    int gid = blockIdx.x * blockDim.x + tid;
    int n = gid >> 5, lane = gid & 31;

    if (tid < HH) acc[tid] = 0.f;
    if (tid == 0) {
        scnt = 0.f;
        g0s = batch[(blockIdx.x * blockDim.x) >> 5];
    }
    __syncthreads();
    int g0 = g0s;

    if (n < NN) {
        float fa[8];
        gather_node(g_bufB, n, lane, fa);
        combine_halves(fa);
        if (lane < 16) {
            int fl = lane;
            float dis = g_dis[n];
            const float* bb = b2 + fl * 8;
            float o[8];
#pragma unroll
            for (int j = 0; j < 8; j++)
                o[j] = fmaxf(fmaf(fa[j], dis, bb[j]), 0.f);
            int g = batch[n];
            if (g == g0) {
#pragma unroll
                for (int j = 0; j < 8; j++)
                    atomicAdd(&acc[fl * 8 + j], o[j]);
                if (fl == 0) atomicAdd(&scnt, 1.f);
            } else {
#pragma unroll
                for (int j = 0; j < 8; j++)
                    atomicAdd(&g_pooled[g * HH + fl * 8 + j], o[j]);
                if (fl == 0) atomicAdd(&g_gcnt[g], 1.f);
            }
        }
    }
    __syncthreads();
    if (tid < HH) {
        float v = acc[tid];
        if (v != 0.f) atomicAdd(&g_pooled[g0 * HH + tid], v);
    }
    if (tid == 0 && scnt > 0.f) atomicAdd(&g_gcnt[g0], scnt);
}

__global__ void k_final(const float* __restrict__ Wl, const float* __restrict__ bl,
                        float* __restrict__ out) {
    int idx = blockIdx.x * blockDim.x + threadIdx.x;
    if (idx >= GG * OUTF) return;
    int g = idx / OUTF, o = idx % OUTF;
    float inv = 1.f / fmaxf(g_gcnt[g], 1.f);
    float s = 0.f;
#pragma unroll 8
    for (int k = 0; k < HH; k++)
        s = fmaf(g_pooled[g * HH + k], Wl[k * OUTF + o], s);
    out[idx] = fmaf(s, inv, bl[o]);
}

// ---------- launch ----------
extern "C" void kernel_launch(void* const* d_in, const int* in_sizes, int n_in,
                              void* d_out, int out_size) {
    const float* x     = (const float*)d_in[0];
    const int*   ei    = (const int*)d_in[1];
    const int*   src   = ei;
    const int*   dst   = ei + EE;
    const int*   batch = (const int*)d_in[2];
    const float* W1    = (const float*)d_in[3];
    const float* b1    = (const float*)d_in[4];
    const float* W2    = (const float*)d_in[5];
    const float* b2    = (const float*)d_in[6];
    const float* Wl    = (const float*)d_in[7];
    const float* bl    = (const float*)d_in[8];
    float* out = (float*)d_out;

    const int T = 256;
    int bN = (NN + T - 1) / T;
    int bE = (EE + T - 1) / T;
    int bW = (NN * 32 + T - 1) / T;       // warp per node
    int bG = (NN + 63) / 64;
    int bF = (GG * OUTF + T - 1) / T;

    k_zero<<<bN, T>>>();
    k_fill<<<bE, T>>>(src, dst);
    k_gemm_in<<<bW, T>>>(x, W1);
    k_agg1<<<bW, T>>>(b1);
    k_gemm2<<<bG, T>>>(W2);
    k_agg_pool<<<bW, T>>>(b2, batch);
    k_final<<<bF, T>>>(Wl, bl, out);
}

// round 6
// speedup vs baseline: 1.2709x; 1.2709x over previous
#include <cuda_runtime.h>
#include <cuda_fp16.h>

#define NN   100000
#define EE   1600000
#define GG   100
#define HH   128
#define OUTF 10
#define CAP  128

typedef unsigned long long u64;

// ---------- device scratch ----------
__device__ __half g_bufA[(size_t)NN * HH];  // hs0 = dis*(x@W1), fp16
__device__ float  g_bufC[(size_t)NN * HH];  // h1 = relu(agg1), fp32
__device__ __half g_bufB[(size_t)NN * HH];  // zs = dis*(h1@W2), fp16
__device__ int    g_pad[(size_t)NN * CAP];
__device__ int    g_cur[NN];
__device__ float  g_dis[NN];
__device__ float  g_pooled[GG * HH];
__device__ float  g_gcnt[GG];

// ---------- f32x2 helpers (for gemm2) ----------
__device__ __forceinline__ u64 fma2(u64 a, u64 b, u64 c) {
    u64 d;
    asm("fma.rn.f32x2 %0, %1, %2, %3;" : "=l"(d) : "l"(a), "l"(b), "l"(c));
    return d;
}
__device__ __forceinline__ u64 splat2(float f) {
    u64 d; unsigned u = __float_as_uint(f);
    asm("mov.b64 %0, {%1, %1};" : "=l"(d) : "r"(u));
    return d;
}
__device__ __forceinline__ void unpack2(u64 v, float& lo, float& hi) {
    unsigned a, b;
    asm("mov.b64 {%0, %1}, %2;" : "=r"(a), "=r"(b) : "l"(v));
    lo = __uint_as_float(a); hi = __uint_as_float(b);
}

__device__ __forceinline__ uint2 pack_h4(float4 o) {
    __half2 lo = __floats2half2_rn(o.x, o.y);
    __half2 hi = __floats2half2_rn(o.z, o.w);
    uint2 r;
    r.x = *(unsigned*)&lo;
    r.y = *(unsigned*)&hi;
    return r;
}

// ---------- gather: full warp, lane owns 4 features (uint2), fp16 acc ----------
__device__ __forceinline__ void hacc2(__half2& h0, __half2& h1, uint2 v) {
    h0 = __hadd2(h0, *(__half2*)&v.x);
    h1 = __hadd2(h1, *(__half2*)&v.y);
}

__device__ __forceinline__ float4 gather_sum_h(const __half* __restrict__ buf,
                                               int n, int lane) {
    int cnt = g_cur[n]; if (cnt > CAP) cnt = CAP;
    const int* lst = g_pad + (size_t)n * CAP;
    const uint2* A = (const uint2*)buf;           // row = 32 uint2
    float4 fa = {0.f, 0.f, 0.f, 0.f};
    const __half2 z = __float2half2_rn(0.f);
    __half2 h0 = z, h1 = z;

    int k = 0;
    for (; k + 8 <= cnt; k += 8) {
        int4 a = *(const int4*)&lst[k];
        int4 b = *(const int4*)&lst[k + 4];
        uint2 v0 = __ldg(&A[a.x * 32 + lane]);
        uint2 v1 = __ldg(&A[a.y * 32 + lane]);
        uint2 v2 = __ldg(&A[a.z * 32 + lane]);
        uint2 v3 = __ldg(&A[a.w * 32 + lane]);
        uint2 v4 = __ldg(&A[b.x * 32 + lane]);
        uint2 v5 = __ldg(&A[b.y * 32 + lane]);
        uint2 v6 = __ldg(&A[b.z * 32 + lane]);
        uint2 v7 = __ldg(&A[b.w * 32 + lane]);
        hacc2(h0, h1, v0); hacc2(h0, h1, v1);
        hacc2(h0, h1, v2); hacc2(h0, h1, v3);
        hacc2(h0, h1, v4); hacc2(h0, h1, v5);
        hacc2(h0, h1, v6); hacc2(h0, h1, v7);
        // flush: <=8 fp16 adds per partial
        float2 f0 = __half22float2(h0), f1 = __half22float2(h1);
        fa.x += f0.x; fa.y += f0.y; fa.z += f1.x; fa.w += f1.y;
        h0 = z; h1 = z;
    }
    for (; k < cnt; k++)
        hacc2(h0, h1, __ldg(&A[__ldg(&lst[k]) * 32 + lane]));
    hacc2(h0, h1, A[n * 32 + lane]);              // self loop (tail partial <=8 adds)
    float2 f0 = __half22float2(h0), f1 = __half22float2(h1);
    fa.x += f0.x; fa.y += f0.y; fa.z += f1.x; fa.w += f1.y;
    return fa;
}

// ---------- kernels ----------
__global__ void k_zero() {
    int i = blockIdx.x * blockDim.x + threadIdx.x;
    if (i < NN) g_cur[i] = 0;
    if (i < GG * HH) g_pooled[i] = 0.f;
    if (i < GG) g_gcnt[i] = 0.f;
}

__global__ void k_fill(const int* __restrict__ src, const int* __restrict__ dst) {
    int e = blockIdx.x * blockDim.x + threadIdx.x;
    if (e < EE) {
        int d = dst[e];
        int p = atomicAdd(&g_cur[d], 1);
        if (p < CAP) g_pad[(size_t)d * CAP + p] = src[e];
    }
}

// hs0 = dis_n * (x_n @ W1) -> fp16; publishes g_dis. Warp per node.
__global__ void __launch_bounds__(256) k_gemm_in(const float* __restrict__ x,
                                                 const float* __restrict__ W1) {
    int gid = blockIdx.x * blockDim.x + threadIdx.x;
    int n = gid >> 5, lane = gid & 31;
    if (n >= NN) return;
    float dis = rsqrtf((float)(g_cur[n] + 1));
    if (lane == 0) g_dis[n] = dis;
    float x0 = x[n * 3 + 0], x1 = x[n * 3 + 1], x2 = x[n * 3 + 2];
    const float4* W = ((const float4*)W1) + lane;
    float4 w0 = W[0], w1 = W[32], w2 = W[64];
    float4 o;
    o.x = dis * fmaf(x0, w0.x, fmaf(x1, w1.x, x2 * w2.x));
    o.y = dis * fmaf(x0, w0.y, fmaf(x1, w1.y, x2 * w2.y));
    o.z = dis * fmaf(x0, w0.z, fmaf(x1, w1.z, x2 * w2.z));
    o.w = dis * fmaf(x0, w0.w, fmaf(x1, w1.w, x2 * w2.w));
    ((uint2*)(g_bufA + (size_t)n * HH))[lane] = pack_h4(o);
}

// Layer-1 aggregate + bias + relu -> h1 (fp32). Warp per node.
__global__ void __launch_bounds__(256) k_agg1(const float* __restrict__ b1) {
    int gid = blockIdx.x * blockDim.x + threadIdx.x;
    int n = gid >> 5, lane = gid & 31;
    if (n >= NN) return;
    float4 a = gather_sum_h(g_bufA, n, lane);
    float dis = g_dis[n];
    float4 b = ((const float4*)b1)[lane];
    float4 o;
    o.x = fmaxf(fmaf(a.x, dis, b.x), 0.f);
    o.y = fmaxf(fmaf(a.y, dis, b.y), 0.f);
    o.z = fmaxf(fmaf(a.z, dis, b.z), 0.f);
    o.w = fmaxf(fmaf(a.w, dis, b.w), 0.f);
    ((float4*)(g_bufC + (size_t)n * HH))[lane] = o;
}

// zs = dis * (h1 @ W2) -> fp16.  64 nodes/block, warp = 8 nodes x 4 cols, f32x2.
__global__ void __launch_bounds__(256) k_gemm2(const float* __restrict__ W2) {
    __shared__ float hs[64][HH];
    int nb0 = blockIdx.x * 64;
    int t = threadIdx.x;

    for (int i = t; i < 64 * 32; i += 256) {
        int r = i >> 5, c4 = i & 31;
        int node = nb0 + r; if (node >= NN) node = NN - 1;
        ((float4*)hs[r])[c4] = ((const float4*)(g_bufC + (size_t)node * HH))[c4];
    }
    __syncthreads();

    int w = t >> 5, lane = t & 31;
    int nb = w * 8;

    u64 acc[8][2];
#pragma unroll
    for (int p = 0; p < 8; p++) { acc[p][0] = 0ull; acc[p][1] = 0ull; }

    const float4* Wr = (const float4*)W2;
#pragma unroll 2
    for (int k = 0; k < HH; k++) {
        float4 wv = __ldg(&Wr[k * 32 + lane]);
        u64 wb0 = ((const u64*)&wv)[0];
        u64 wb1 = ((const u64*)&wv)[1];
#pragma unroll
        for (int p = 0; p < 8; p++) {
            u64 ha = splat2(hs[nb + p][k]);
            acc[p][0] = fma2(ha, wb0, acc[p][0]);
            acc[p][1] = fma2(ha, wb1, acc[p][1]);
        }
    }

#pragma unroll
    for (int p = 0; p < 8; p++) {
        int node = nb0 + nb + p;
        if (node >= NN) break;
        float dis = g_dis[node];
        float4 o;
        unpack2(acc[p][0], o.x, o.y);
        unpack2(acc[p][1], o.z, o.w);
        o.x *= dis; o.y *= dis; o.z *= dis; o.w *= dis;
        ((uint2*)(g_bufB + (size_t)node * HH))[lane] = pack_h4(o);
    }
}

// Layer-2 aggregate + relu + fused mean-pool (block smem reduction).
__global__ void __launch_bounds__(256) k_agg_pool(const float* __restrict__ b2,
                                                   const int* __restrict__ batch) {
    __shared__ float acc[HH];
    __shared__ float scnt;
    __shared__ int g0s;
    int tid = threadIdx.x;
    int gid = blockIdx.x * blockDim.x + tid;
    int n = gid >> 5, lane = gid & 31;

    if (tid < HH) acc[tid] = 0.f;
    if (tid == 0) {
        scnt = 0.f;
        g0s = batch[(blockIdx.x * blockDim.x) >> 5];
    }
    __syncthreads();
    int g0 = g0s;

    if (n < NN) {
        float4 a = gather_sum_h(g_bufB, n, lane);
        float dis = g_dis[n];
        float4 b = ((const float4*)b2)[lane];
        float4 o;
        o.x = fmaxf(fmaf(a.x, dis, b.x), 0.f);
        o.y = fmaxf(fmaf(a.y, dis, b.y), 0.f);
        o.z = fmaxf(fmaf(a.z, dis, b.z), 0.f);
        o.w = fmaxf(fmaf(a.w, dis, b.w), 0.f);
        int g = batch[n];
        if (g == g0) {
            atomicAdd(&acc[lane * 4 + 0], o.x);
            atomicAdd(&acc[lane * 4 + 1], o.y);
            atomicAdd(&acc[lane * 4 + 2], o.z);
            atomicAdd(&acc[lane * 4 + 3], o.w);
            if (lane == 0) atomicAdd(&scnt, 1.f);
        } else {
            atomicAdd(&g_pooled[g * HH + lane * 4 + 0], o.x);
            atomicAdd(&g_pooled[g * HH + lane * 4 + 1], o.y);
            atomicAdd(&g_pooled[g * HH + lane * 4 + 2], o.z);
            atomicAdd(&g_pooled[g * HH + lane * 4 + 3], o.w);
            if (lane == 0) atomicAdd(&g_gcnt[g], 1.f);
        }
    }
    __syncthreads();
    if (tid < HH) {
        float v = acc[tid];
        if (v != 0.f) atomicAdd(&g_pooled[g0 * HH + tid], v);
    }
    if (tid == 0 && scnt > 0.f) atomicAdd(&g_gcnt[g0], scnt);
}

__global__ void k_final(const float* __restrict__ Wl, const float* __restrict__ bl,
                        float* __restrict__ out) {
    int idx = blockIdx.x * blockDim.x + threadIdx.x;
    if (idx >= GG * OUTF) return;
    int g = idx / OUTF, o = idx % OUTF;
    float inv = 1.f / fmaxf(g_gcnt[g], 1.f);
    float s = 0.f;
#pragma unroll 8
    for (int k = 0; k < HH; k++)
        s = fmaf(g_pooled[g * HH + k], Wl[k * OUTF + o], s);
    out[idx] = fmaf(s, inv, bl[o]);
}

// ---------- launch ----------
extern "C" void kernel_launch(void* const* d_in, const int* in_sizes, int n_in,
                              void* d_out, int out_size) {
    const float* x     = (const float*)d_in[0];
    const int*   ei    = (const int*)d_in[1];
    const int*   src   = ei;
    const int*   dst   = ei + EE;
    const int*   batch = (const int*)d_in[2];
    const float* W1    = (const float*)d_in[3];
    const float* b1    = (const float*)d_in[4];
    const float* W2    = (const float*)d_in[5];
    const float* b2    = (const float*)d_in[6];
    const float* Wl    = (const float*)d_in[7];
    const float* bl    = (const float*)d_in[8];
    float* out = (float*)d_out;

    const int T = 256;
    int bN = (NN + T - 1) / T;
    int bE = (EE + T - 1) / T;
    int bW = (NN * 32 + T - 1) / T;       // warp per node
    int bG = (NN + 63) / 64;
    int bF = (GG * OUTF + T - 1) / T;

    k_zero<<<bN, T>>>();
    k_fill<<<bE, T>>>(src, dst);
    k_gemm_in<<<bW, T>>>(x, W1);
    k_agg1<<<bW, T>>>(b1);
    k_gemm2<<<bG, T>>>(W2);
    k_agg_pool<<<bW, T>>>(b2, batch);
    k_final<<<bF, T>>>(Wl, bl, out);
}

// round 7
// speedup vs baseline: 1.7040x; 1.3408x over previous
#include <cuda_runtime.h>
#include <cuda_fp16.h>

#define NN   100000
#define EE   1600000
#define GG   100
#define HH   128
#define OUTF 10
#define CAP  128
#define PITCH 136   // smem row pitch in halves (272B: conflict-free for ldmatrix)

typedef unsigned long long u64;

// ---------- device scratch ----------
__device__ __half g_bufA[(size_t)NN * HH];   // hs0 = dis*(x@W1), fp16
__device__ __half g_bufCh[(size_t)NN * HH];  // h1 = relu(agg1), fp16
__device__ __half g_bufB[(size_t)NN * HH];   // zs = dis*(h1@W2), fp16
__device__ __half g_W2h[HH * HH];            // W2 in fp16
__device__ int    g_pad[(size_t)NN * CAP];
__device__ int    g_cur[NN];
__device__ float  g_dis[NN];
__device__ float  g_pooled[GG * HH];
__device__ float  g_gcnt[GG];

__device__ __forceinline__ unsigned smem_u32(const void* p) {
    return (unsigned)__cvta_generic_to_shared(p);
}

__device__ __forceinline__ uint2 pack_h4(float4 o) {
    __half2 lo = __floats2half2_rn(o.x, o.y);
    __half2 hi = __floats2half2_rn(o.z, o.w);
    uint2 r;
    r.x = *(unsigned*)&lo;
    r.y = *(unsigned*)&hi;
    return r;
}

// ---------- mma / ldmatrix ----------
__device__ __forceinline__ void mma16816(float d[4], const unsigned a[4],
                                         const unsigned b[2], const float c[4]) {
    asm volatile(
        "mma.sync.aligned.m16n8k16.row.col.f32.f16.f16.f32 "
        "{%0,%1,%2,%3}, {%4,%5,%6,%7}, {%8,%9}, {%10,%11,%12,%13};\n"
        : "=f"(d[0]), "=f"(d[1]), "=f"(d[2]), "=f"(d[3])
        : "r"(a[0]), "r"(a[1]), "r"(a[2]), "r"(a[3]),
          "r"(b[0]), "r"(b[1]),
          "f"(c[0]), "f"(c[1]), "f"(c[2]), "f"(c[3]));
}
__device__ __forceinline__ void ldsm_x4(unsigned r[4], unsigned addr) {
    asm volatile("ldmatrix.sync.aligned.m8n8.x4.shared.b16 {%0,%1,%2,%3}, [%4];\n"
        : "=r"(r[0]), "=r"(r[1]), "=r"(r[2]), "=r"(r[3]) : "r"(addr));
}
__device__ __forceinline__ void ldsm_x2_t(unsigned r[2], unsigned addr) {
    asm volatile("ldmatrix.sync.aligned.m8n8.x2.trans.shared.b16 {%0,%1}, [%2];\n"
        : "=r"(r[0]), "=r"(r[1]) : "r"(addr));
}

// ---------- gather: full warp, lane owns 4 features (uint2), fp16 acc ----------
__device__ __forceinline__ void hacc2(__half2& h0, __half2& h1, uint2 v) {
    h0 = __hadd2(h0, *(__half2*)&v.x);
    h1 = __hadd2(h1, *(__half2*)&v.y);
}

__device__ __forceinline__ float4 gather_sum_h(const __half* __restrict__ buf,
                                               int n, int lane) {
    int cnt = g_cur[n]; if (cnt > CAP) cnt = CAP;
    const int* lst = g_pad + (size_t)n * CAP;
    const uint2* A = (const uint2*)buf;           // row = 32 uint2
    float4 fa = {0.f, 0.f, 0.f, 0.f};
    const __half2 z = __float2half2_rn(0.f);
    __half2 h0 = z, h1 = z;

    int k = 0;
    for (; k + 8 <= cnt; k += 8) {
        int4 a = *(const int4*)&lst[k];
        int4 b = *(const int4*)&lst[k + 4];
        uint2 v0 = __ldg(&A[a.x * 32 + lane]);
        uint2 v1 = __ldg(&A[a.y * 32 + lane]);
        uint2 v2 = __ldg(&A[a.z * 32 + lane]);
        uint2 v3 = __ldg(&A[a.w * 32 + lane]);
        uint2 v4 = __ldg(&A[b.x * 32 + lane]);
        uint2 v5 = __ldg(&A[b.y * 32 + lane]);
        uint2 v6 = __ldg(&A[b.z * 32 + lane]);
        uint2 v7 = __ldg(&A[b.w * 32 + lane]);
        hacc2(h0, h1, v0); hacc2(h0, h1, v1);
        hacc2(h0, h1, v2); hacc2(h0, h1, v3);
        hacc2(h0, h1, v4); hacc2(h0, h1, v5);
        hacc2(h0, h1, v6); hacc2(h0, h1, v7);
        float2 f0 = __half22float2(h0), f1 = __half22float2(h1);
        fa.x += f0.x; fa.y += f0.y; fa.z += f1.x; fa.w += f1.y;
        h0 = z; h1 = z;
    }
    for (; k < cnt; k++)
        hacc2(h0, h1, __ldg(&A[__ldg(&lst[k]) * 32 + lane]));
    hacc2(h0, h1, A[n * 32 + lane]);              // self loop
    float2 f0 = __half22float2(h0), f1 = __half22float2(h1);
    fa.x += f0.x; fa.y += f0.y; fa.z += f1.x; fa.w += f1.y;
    return fa;
}

// ---------- kernels ----------
__global__ void k_zero() {
    int i = blockIdx.x * blockDim.x + threadIdx.x;
    if (i < NN) g_cur[i] = 0;
    if (i < GG * HH) g_pooled[i] = 0.f;
    if (i < GG) g_gcnt[i] = 0.f;
}

__global__ void k_w2h(const float* __restrict__ W2) {
    int i = blockIdx.x * blockDim.x + threadIdx.x;
    if (i < HH * HH) g_W2h[i] = __float2half_rn(W2[i]);
}

// 4 edges per thread, vectorized index loads
__global__ void k_fill(const int* __restrict__ src, const int* __restrict__ dst) {
    int i = blockIdx.x * blockDim.x + threadIdx.x;
    if (i >= EE / 4) return;
    int4 d4 = __ldg(&((const int4*)dst)[i]);
    int4 s4 = __ldg(&((const int4*)src)[i]);
    int p0 = atomicAdd(&g_cur[d4.x], 1); if (p0 < CAP) g_pad[d4.x * CAP + p0] = s4.x;
    int p1 = atomicAdd(&g_cur[d4.y], 1); if (p1 < CAP) g_pad[d4.y * CAP + p1] = s4.y;
    int p2 = atomicAdd(&g_cur[d4.z], 1); if (p2 < CAP) g_pad[d4.z * CAP + p2] = s4.z;
    int p3 = atomicAdd(&g_cur[d4.w], 1); if (p3 < CAP) g_pad[d4.w * CAP + p3] = s4.w;
}

// hs0 = dis_n * (x_n @ W1) -> fp16; publishes g_dis. Warp per node.
__global__ void __launch_bounds__(256) k_gemm_in(const float* __restrict__ x,
                                                 const float* __restrict__ W1) {
    int gid = blockIdx.x * blockDim.x + threadIdx.x;
    int n = gid >> 5, lane = gid & 31;
    if (n >= NN) return;
    float dis = rsqrtf((float)(g_cur[n] + 1));
    if (lane == 0) g_dis[n] = dis;
    float x0 = x[n * 3 + 0], x1 = x[n * 3 + 1], x2 = x[n * 3 + 2];
    const float4* W = ((const float4*)W1) + lane;
    float4 w0 = W[0], w1 = W[32], w2 = W[64];
    float4 o;
    o.x = dis * fmaf(x0, w0.x, fmaf(x1, w1.x, x2 * w2.x));
    o.y = dis * fmaf(x0, w0.y, fmaf(x1, w1.y, x2 * w2.y));
    o.z = dis * fmaf(x0, w0.z, fmaf(x1, w1.z, x2 * w2.z));
    o.w = dis * fmaf(x0, w0.w, fmaf(x1, w1.w, x2 * w2.w));
    ((uint2*)(g_bufA + (size_t)n * HH))[lane] = pack_h4(o);
}

// Layer-1 aggregate + bias + relu -> h1 (fp16). Warp per node.
__global__ void __launch_bounds__(256) k_agg1(const float* __restrict__ b1) {
    int gid = blockIdx.x * blockDim.x + threadIdx.x;
    int n = gid >> 5, lane = gid & 31;
    if (n >= NN) return;
    float4 a = gather_sum_h(g_bufA, n, lane);
    float dis = g_dis[n];
    float4 b = ((const float4*)b1)[lane];
    float4 o;
    o.x = fmaxf(fmaf(a.x, dis, b.x), 0.f);
    o.y = fmaxf(fmaf(a.y, dis, b.y), 0.f);
    o.z = fmaxf(fmaf(a.z, dis, b.z), 0.f);
    o.w = fmaxf(fmaf(a.w, dis, b.w), 0.f);
    ((uint2*)(g_bufCh + (size_t)n * HH))[lane] = pack_h4(o);
}

// zs = dis * (h1 @ W2) -> fp16, via HMMA m16n8k16.
// Block: 256 thr = 8 warps; 128 nodes/block; warp = 16 node-rows x 128 cols.
__global__ void __launch_bounds__(256) k_gemm2_mma() {
    extern __shared__ __half sh[];
    __half* sh_h = sh;                  // [128][PITCH]
    __half* sh_w = sh + 128 * PITCH;    // [128][PITCH]
    int t = threadIdx.x;
    int nb0 = blockIdx.x * 128;

    // stage h1 tile + W2 (uint4 = 8 halves per chunk)
    for (int i = t; i < 128 * 16; i += 256) {
        int r = i >> 4, c8 = (i & 15) * 8;
        int node = nb0 + r; if (node >= NN) node = NN - 1;
        *(uint4*)&sh_h[r * PITCH + c8] = *(const uint4*)&g_bufCh[(size_t)node * HH + c8];
        *(uint4*)&sh_w[r * PITCH + c8] = *(const uint4*)&g_W2h[r * HH + c8];
    }
    __syncthreads();

    int w = t >> 5, lane = t & 31;
    int r0 = w * 16;

    float acc[16][4];
#pragma unroll
    for (int j = 0; j < 16; j++)
#pragma unroll
        for (int q = 0; q < 4; q++) acc[j][q] = 0.f;

    int a_row = r0 + (lane & 15);
    int a_col = (lane >> 4) * 8;
    int b_lane = lane & 15;

    for (int kc = 0; kc < 8; kc++) {
        int k0 = kc * 16;
        unsigned a[4];
        ldsm_x4(a, smem_u32(&sh_h[a_row * PITCH + k0 + a_col]));
        unsigned b_base = smem_u32(&sh_w[(k0 + b_lane) * PITCH]);
#pragma unroll
        for (int j = 0; j < 16; j++) {
            unsigned b[2];
            ldsm_x2_t(b, b_base + j * 8 * sizeof(__half));
            mma16816(acc[j], a, b, acc[j]);
        }
    }

    // epilogue: D layout: d0,d1 -> row lane/4, cols 2*(lane%4)+{0,1};
    //                     d2,d3 -> row lane/4+8, same cols
    int lrow = lane >> 2;
    int lcol = (lane & 3) * 2;
    int node0 = nb0 + r0 + lrow;
    int node1 = node0 + 8;
    float dis0 = (node0 < NN) ? g_dis[node0] : 0.f;
    float dis1 = (node1 < NN) ? g_dis[node1] : 0.f;
#pragma unroll
    for (int j = 0; j < 16; j++) {
        if (node0 < NN) {
            __half2 p = __floats2half2_rn(acc[j][0] * dis0, acc[j][1] * dis0);
            *(__half2*)&g_bufB[(size_t)node0 * HH + j * 8 + lcol] = p;
        }
        if (node1 < NN) {
            __half2 p = __floats2half2_rn(acc[j][2] * dis1, acc[j][3] * dis1);
            *(__half2*)&g_bufB[(size_t)node1 * HH + j * 8 + lcol] = p;
        }
    }
}

// Layer-2 aggregate + relu + fused mean-pool (block smem reduction).
__global__ void __launch_bounds__(256) k_agg_pool(const float* __restrict__ b2,
                                                   const int* __restrict__ batch) {
    __shared__ float acc[HH];
    __shared__ float scnt;
    __shared__ int g0s;
    int tid = threadIdx.x;
    int gid = blockIdx.x * blockDim.x + tid;
    int n = gid >> 5, lane = gid & 31;

    if (tid < HH) acc[tid] = 0.f;
    if (tid == 0) {
        scnt = 0.f;
        g0s = batch[(blockIdx.x * blockDim.x) >> 5];
    }
    __syncthreads();
    int g0 = g0s;

    if (n < NN) {
        float4 a = gather_sum_h(g_bufB, n, lane);
        float dis = g_dis[n];
        float4 b = ((const float4*)b2)[lane];
        float4 o;
        o.x = fmaxf(fmaf(a.x, dis, b.x), 0.f);
        o.y = fmaxf(fmaf(a.y, dis, b.y), 0.f);
        o.z = fmaxf(fmaf(a.z, dis, b.z), 0.f);
        o.w = fmaxf(fmaf(a.w, dis, b.w), 0.f);
        int g = batch[n];
        if (g == g0) {
            atomicAdd(&acc[lane * 4 + 0], o.x);
            atomicAdd(&acc[lane * 4 + 1], o.y);
            atomicAdd(&acc[lane * 4 + 2], o.z);
            atomicAdd(&acc[lane * 4 + 3], o.w);
            if (lane == 0) atomicAdd(&scnt, 1.f);
        } else {
            atomicAdd(&g_pooled[g * HH + lane * 4 + 0], o.x);
            atomicAdd(&g_pooled[g * HH + lane * 4 + 1], o.y);
            atomicAdd(&g_pooled[g * HH + lane * 4 + 2], o.z);
            atomicAdd(&g_pooled[g * HH + lane * 4 + 3], o.w);
            if (lane == 0) atomicAdd(&g_gcnt[g], 1.f);
        }
    }
    __syncthreads();
    if (tid < HH) {
        float v = acc[tid];
        if (v != 0.f) atomicAdd(&g_pooled[g0 * HH + tid], v);
    }
    if (tid == 0 && scnt > 0.f) atomicAdd(&g_gcnt[g0], scnt);
}

__global__ void k_final(const float* __restrict__ Wl, const float* __restrict__ bl,
                        float* __restrict__ out) {
    int idx = blockIdx.x * blockDim.x + threadIdx.x;
    if (idx >= GG * OUTF) return;
    int g = idx / OUTF, o = idx % OUTF;
    float inv = 1.f / fmaxf(g_gcnt[g], 1.f);
    float s = 0.f;
#pragma unroll 8
    for (int k = 0; k < HH; k++)
        s = fmaf(g_pooled[g * HH + k], Wl[k * OUTF + o], s);
    out[idx] = fmaf(s, inv, bl[o]);
}

// ---------- launch ----------
extern "C" void kernel_launch(void* const* d_in, const int* in_sizes, int n_in,
                              void* d_out, int out_size) {
    const float* x     = (const float*)d_in[0];
    const int*   ei    = (const int*)d_in[1];
    const int*   src   = ei;
    const int*   dst   = ei + EE;
    const int*   batch = (const int*)d_in[2];
    const float* W1    = (const float*)d_in[3];
    const float* b1    = (const float*)d_in[4];
    const float* W2    = (const float*)d_in[5];
    const float* b2    = (const float*)d_in[6];
    const float* Wl    = (const float*)d_in[7];
    const float* bl    = (const float*)d_in[8];
    float* out = (float*)d_out;

    const int SMEM_MMA = 2 * 128 * PITCH * (int)sizeof(__half);   // 69632
    cudaFuncSetAttribute(k_gemm2_mma,
                         cudaFuncAttributeMaxDynamicSharedMemorySize, SMEM_MMA);

    const int T = 256;
    int bN = (NN + T - 1) / T;
    int bE = (EE / 4 + T - 1) / T;
    int bW = (NN * 32 + T - 1) / T;       // warp per node
    int bM = (NN + 127) / 128;            // mma tiles
    int bF = (GG * OUTF + T - 1) / T;

    k_zero<<<bN, T>>>();
    k_w2h<<<(HH * HH + T - 1) / T, T>>>(W2);
    k_fill<<<bE, T>>>(src, dst);
    k_gemm_in<<<bW, T>>>(x, W1);
    k_agg1<<<bW, T>>>(b1);
    k_gemm2_mma<<<bM, T, SMEM_MMA>>>();
    k_agg_pool<<<bW, T>>>(b2, batch);
    k_final<<<bF, T>>>(Wl, bl, out);
}

// round 8
// speedup vs baseline: 1.7512x; 1.0277x over previous
#include <cuda_runtime.h>
#include <cuda_fp16.h>

#define NN   100000
#define EE   1600000
#define GG   100
#define HH   128
#define OUTF 10
#define CAP  128
#define PITCH 136   // smem row pitch in halves (272B: conflict-free for ldmatrix)

typedef unsigned long long u64;

// ---------- device scratch ----------
__device__ __half g_bufA[(size_t)NN * HH];   // hs0 = dis*(x@W1), fp16
__device__ __half g_bufCh[(size_t)NN * HH];  // h1 = relu(agg1), fp16
__device__ __half g_bufB[(size_t)NN * HH];   // zs = dis*(h1@W2), fp16
__device__ __half g_W2h[HH * HH];            // W2 in fp16
__device__ int    g_pad[(size_t)NN * CAP];   // scaled src indices (src*32)
__device__ int    g_cur[NN];
__device__ float  g_dis[NN];
__device__ float  g_pooled[GG * HH];
__device__ float  g_gcnt[GG];

__device__ __forceinline__ unsigned smem_u32(const void* p) {
    return (unsigned)__cvta_generic_to_shared(p);
}

__device__ __forceinline__ uint2 pack_h4(float4 o) {
    __half2 lo = __floats2half2_rn(o.x, o.y);
    __half2 hi = __floats2half2_rn(o.z, o.w);
    uint2 r;
    r.x = *(unsigned*)&lo;
    r.y = *(unsigned*)&hi;
    return r;
}

// ---------- mma / ldmatrix ----------
__device__ __forceinline__ void mma16816(float d[4], const unsigned a[4],
                                         const unsigned b[2], const float c[4]) {
    asm volatile(
        "mma.sync.aligned.m16n8k16.row.col.f32.f16.f16.f32 "
        "{%0,%1,%2,%3}, {%4,%5,%6,%7}, {%8,%9}, {%10,%11,%12,%13};\n"
        : "=f"(d[0]), "=f"(d[1]), "=f"(d[2]), "=f"(d[3])
        : "r"(a[0]), "r"(a[1]), "r"(a[2]), "r"(a[3]),
          "r"(b[0]), "r"(b[1]),
          "f"(c[0]), "f"(c[1]), "f"(c[2]), "f"(c[3]));
}
__device__ __forceinline__ void ldsm_x4(unsigned r[4], unsigned addr) {
    asm volatile("ldmatrix.sync.aligned.m8n8.x4.shared.b16 {%0,%1,%2,%3}, [%4];\n"
        : "=r"(r[0]), "=r"(r[1]), "=r"(r[2]), "=r"(r[3]) : "r"(addr));
}
__device__ __forceinline__ void ldsm_x2_t(unsigned r[2], unsigned addr) {
    asm volatile("ldmatrix.sync.aligned.m8n8.x2.trans.shared.b16 {%0,%1}, [%2];\n"
        : "=r"(r[0]), "=r"(r[1]) : "r"(addr));
}

// ---------- gather: full warp, lane owns 4 features (uint2), fp16 acc ----------
// g_pad holds PRE-SCALED indices (src*32), so row address = idx + lane.
__device__ __forceinline__ void hacc2(__half2& h0, __half2& h1, uint2 v) {
    h0 = __hadd2(h0, *(__half2*)&v.x);
    h1 = __hadd2(h1, *(__half2*)&v.y);
}

__device__ __forceinline__ float4 gather_sum_h(const __half* __restrict__ buf,
                                               int n, int lane) {
    int cnt = g_cur[n]; if (cnt > CAP) cnt = CAP;
    const int* lst = g_pad + (size_t)n * CAP;
    const uint2* A = (const uint2*)buf;           // row = 32 uint2
    float4 fa = {0.f, 0.f, 0.f, 0.f};
    const __half2 z = __float2half2_rn(0.f);
    __half2 h0 = z, h1 = z;

    int k = 0, sf = 0;
    for (; k + 8 <= cnt; k += 8) {
        int4 a = *(const int4*)&lst[k];
        int4 b = *(const int4*)&lst[k + 4];
        uint2 v0 = __ldg(&A[a.x + lane]);
        uint2 v1 = __ldg(&A[a.y + lane]);
        uint2 v2 = __ldg(&A[a.z + lane]);
        uint2 v3 = __ldg(&A[a.w + lane]);
        uint2 v4 = __ldg(&A[b.x + lane]);
        uint2 v5 = __ldg(&A[b.y + lane]);
        uint2 v6 = __ldg(&A[b.z + lane]);
        uint2 v7 = __ldg(&A[b.w + lane]);
        hacc2(h0, h1, v0); hacc2(h0, h1, v1);
        hacc2(h0, h1, v2); hacc2(h0, h1, v3);
        hacc2(h0, h1, v4); hacc2(h0, h1, v5);
        hacc2(h0, h1, v6); hacc2(h0, h1, v7);
        if (++sf == 2) {                          // flush every 16 edges
            float2 f0 = __half22float2(h0), f1 = __half22float2(h1);
            fa.x += f0.x; fa.y += f0.y; fa.z += f1.x; fa.w += f1.y;
            h0 = z; h1 = z; sf = 0;
        }
    }
    for (; k < cnt; k++)
        hacc2(h0, h1, __ldg(&A[__ldg(&lst[k]) + lane]));
    hacc2(h0, h1, A[n * 32 + lane]);              // self loop (partial <=16 adds)
    float2 f0 = __half22float2(h0), f1 = __half22float2(h1);
    fa.x += f0.x; fa.y += f0.y; fa.z += f1.x; fa.w += f1.y;
    return fa;
}

// ---------- kernels ----------
// zero counters + pooled accumulators + convert W2 to fp16
__global__ void k_prep(const float* __restrict__ W2) {
    int i = blockIdx.x * blockDim.x + threadIdx.x;
    if (i < NN) g_cur[i] = 0;
    if (i < GG * HH) g_pooled[i] = 0.f;
    if (i < GG) g_gcnt[i] = 0.f;
    if (i < HH * HH) g_W2h[i] = __float2half_rn(W2[i]);
}

// 4 edges per thread, vectorized index loads; stores src*32 (scaled)
__global__ void k_fill(const int* __restrict__ src, const int* __restrict__ dst) {
    int i = blockIdx.x * blockDim.x + threadIdx.x;
    if (i >= EE / 4) return;
    int4 d4 = __ldg(&((const int4*)dst)[i]);
    int4 s4 = __ldg(&((const int4*)src)[i]);
    int p0 = atomicAdd(&g_cur[d4.x], 1); if (p0 < CAP) g_pad[d4.x * CAP + p0] = s4.x * 32;
    int p1 = atomicAdd(&g_cur[d4.y], 1); if (p1 < CAP) g_pad[d4.y * CAP + p1] = s4.y * 32;
    int p2 = atomicAdd(&g_cur[d4.z], 1); if (p2 < CAP) g_pad[d4.z * CAP + p2] = s4.z * 32;
    int p3 = atomicAdd(&g_cur[d4.w], 1); if (p3 < CAP) g_pad[d4.w * CAP + p3] = s4.w * 32;
}

// hs0 = dis_n * (x_n @ W1) -> fp16; publishes g_dis. Warp per 4 nodes.
__global__ void __launch_bounds__(256) k_gemm_in(const float* __restrict__ x,
                                                 const float* __restrict__ W1) {
    int gid = blockIdx.x * blockDim.x + threadIdx.x;
    int w = gid >> 5, lane = gid & 31;
    int n0 = w * 4;
    if (n0 >= NN) return;
    const float4* W = ((const float4*)W1) + lane;
    float4 w0 = W[0], w1 = W[32], w2 = W[64];
#pragma unroll
    for (int p = 0; p < 4; p++) {
        int n = n0 + p;
        float dis = rsqrtf((float)(g_cur[n] + 1));
        if (lane == 0) g_dis[n] = dis;
        float x0 = __ldg(&x[n * 3 + 0]);
        float x1 = __ldg(&x[n * 3 + 1]);
        float x2 = __ldg(&x[n * 3 + 2]);
        float4 o;
        o.x = dis * fmaf(x0, w0.x, fmaf(x1, w1.x, x2 * w2.x));
        o.y = dis * fmaf(x0, w0.y, fmaf(x1, w1.y, x2 * w2.y));
        o.z = dis * fmaf(x0, w0.z, fmaf(x1, w1.z, x2 * w2.z));
        o.w = dis * fmaf(x0, w0.w, fmaf(x1, w1.w, x2 * w2.w));
        ((uint2*)(g_bufA + (size_t)n * HH))[lane] = pack_h4(o);
    }
}

// Layer-1 aggregate + bias + relu -> h1 (fp16). Warp per node.
__global__ void __launch_bounds__(256) k_agg1(const float* __restrict__ b1) {
    int gid = blockIdx.x * blockDim.x + threadIdx.x;
    int n = gid >> 5, lane = gid & 31;
    if (n >= NN) return;
    float4 a = gather_sum_h(g_bufA, n, lane);
    float dis = g_dis[n];
    float4 b = ((const float4*)b1)[lane];
    float4 o;
    o.x = fmaxf(fmaf(a.x, dis, b.x), 0.f);
    o.y = fmaxf(fmaf(a.y, dis, b.y), 0.f);
    o.z = fmaxf(fmaf(a.z, dis, b.z), 0.f);
    o.w = fmaxf(fmaf(a.w, dis, b.w), 0.f);
    ((uint2*)(g_bufCh + (size_t)n * HH))[lane] = pack_h4(o);
}

// zs = dis * (h1 @ W2) -> fp16, via HMMA m16n8k16.
__global__ void __launch_bounds__(256) k_gemm2_mma() {
    extern __shared__ __half sh[];
    __half* sh_h = sh;                  // [128][PITCH]
    __half* sh_w = sh + 128 * PITCH;    // [128][PITCH]
    int t = threadIdx.x;
    int nb0 = blockIdx.x * 128;

    for (int i = t; i < 128 * 16; i += 256) {
        int r = i >> 4, c8 = (i & 15) * 8;
        int node = nb0 + r; if (node >= NN) node = NN - 1;
        *(uint4*)&sh_h[r * PITCH + c8] = *(const uint4*)&g_bufCh[(size_t)node * HH + c8];
        *(uint4*)&sh_w[r * PITCH + c8] = *(const uint4*)&g_W2h[r * HH + c8];
    }
    __syncthreads();

    int w = t >> 5, lane = t & 31;
    int r0 = w * 16;

    float acc[16][4];
#pragma unroll
    for (int j = 0; j < 16; j++)
#pragma unroll
        for (int q = 0; q < 4; q++) acc[j][q] = 0.f;

    int a_row = r0 + (lane & 15);
    int a_col = (lane >> 4) * 8;
    int b_lane = lane & 15;

    for (int kc = 0; kc < 8; kc++) {
        int k0 = kc * 16;
        unsigned a[4];
        ldsm_x4(a, smem_u32(&sh_h[a_row * PITCH + k0 + a_col]));
        unsigned b_base = smem_u32(&sh_w[(k0 + b_lane) * PITCH]);
#pragma unroll
        for (int j = 0; j < 16; j++) {
            unsigned b[2];
            ldsm_x2_t(b, b_base + j * 8 * sizeof(__half));
            mma16816(acc[j], a, b, acc[j]);
        }
    }

    int lrow = lane >> 2;
    int lcol = (lane & 3) * 2;
    int node0 = nb0 + r0 + lrow;
    int node1 = node0 + 8;
    float dis0 = (node0 < NN) ? g_dis[node0] : 0.f;
    float dis1 = (node1 < NN) ? g_dis[node1] : 0.f;
#pragma unroll
    for (int j = 0; j < 16; j++) {
        if (node0 < NN) {
            __half2 p = __floats2half2_rn(acc[j][0] * dis0, acc[j][1] * dis0);
            *(__half2*)&g_bufB[(size_t)node0 * HH + j * 8 + lcol] = p;
        }
        if (node1 < NN) {
            __half2 p = __floats2half2_rn(acc[j][2] * dis1, acc[j][3] * dis1);
            *(__half2*)&g_bufB[(size_t)node1 * HH + j * 8 + lcol] = p;
        }
    }
}

// Layer-2 aggregate + relu + fused mean-pool (block smem reduction).
__global__ void __launch_bounds__(256) k_agg_pool(const float* __restrict__ b2,
                                                   const int* __restrict__ batch) {
    __shared__ float acc[HH];
    __shared__ float scnt;
    __shared__ int g0s;
    int tid = threadIdx.x;
    int gid = blockIdx.x * blockDim.x + tid;
    int n = gid >> 5, lane = gid & 31;

    if (tid < HH) acc[tid] = 0.f;
    if (tid == 0) {
        scnt = 0.f;
        g0s = batch[(blockIdx.x * blockDim.x) >> 5];
    }
    __syncthreads();
    int g0 = g0s;

    if (n < NN) {
        float4 a = gather_sum_h(g_bufB, n, lane);
        float dis = g_dis[n];
        float4 b = ((const float4*)b2)[lane];
        float4 o;
        o.x = fmaxf(fmaf(a.x, dis, b.x), 0.f);
        o.y = fmaxf(fmaf(a.y, dis, b.y), 0.f);
        o.z = fmaxf(fmaf(a.z, dis, b.z), 0.f);
        o.w = fmaxf(fmaf(a.w, dis, b.w), 0.f);
        int g = batch[n];
        if (g == g0) {
            atomicAdd(&acc[lane * 4 + 0], o.x);
            atomicAdd(&acc[lane * 4 + 1], o.y);
            atomicAdd(&acc[lane * 4 + 2], o.z);
            atomicAdd(&acc[lane * 4 + 3], o.w);
            if (lane == 0) atomicAdd(&scnt, 1.f);
        } else {
            atomicAdd(&g_pooled[g * HH + lane * 4 + 0], o.x);
            atomicAdd(&g_pooled[g * HH + lane * 4 + 1], o.y);
            atomicAdd(&g_pooled[g * HH + lane * 4 + 2], o.z);
            atomicAdd(&g_pooled[g * HH + lane * 4 + 3], o.w);
            if (lane == 0) atomicAdd(&g_gcnt[g], 1.f);
        }
    }
    __syncthreads();
    if (tid < HH) {
        float v = acc[tid];
        if (v != 0.f) atomicAdd(&g_pooled[g0 * HH + tid], v);
    }
    if (tid == 0 && scnt > 0.f) atomicAdd(&g_gcnt[g0], scnt);
}

__global__ void k_final(const float* __restrict__ Wl, const float* __restrict__ bl,
                        float* __restrict__ out) {
    int idx = blockIdx.x * blockDim.x + threadIdx.x;
    if (idx >= GG * OUTF) return;
    int g = idx / OUTF, o = idx % OUTF;
    float inv = 1.f / fmaxf(g_gcnt[g], 1.f);
    float s = 0.f;
#pragma unroll 8
    for (int k = 0; k < HH; k++)
        s = fmaf(g_pooled[g * HH + k], Wl[k * OUTF + o], s);
    out[idx] = fmaf(s, inv, bl[o]);
}

// ---------- launch ----------
extern "C" void kernel_launch(void* const* d_in, const int* in_sizes, int n_in,
                              void* d_out, int out_size) {
    const float* x     = (const float*)d_in[0];
    const int*   ei    = (const int*)d_in[1];
    const int*   src   = ei;
    const int*   dst   = ei + EE;
    const int*   batch = (const int*)d_in[2];
    const float* W1    = (const float*)d_in[3];
    const float* b1    = (const float*)d_in[4];
    const float* W2    = (const float*)d_in[5];
    const float* b2    = (const float*)d_in[6];
    const float* Wl    = (const float*)d_in[7];
    const float* bl    = (const float*)d_in[8];
    float* out = (float*)d_out;

    const int SMEM_MMA = 2 * 128 * PITCH * (int)sizeof(__half);   // 69632
    cudaFuncSetAttribute(k_gemm2_mma,
                         cudaFuncAttributeMaxDynamicSharedMemorySize, SMEM_MMA);

    const int T = 256;
    int bN = (NN + T - 1) / T;
    int bE = (EE / 4 + T - 1) / T;
    int bW = (NN * 32 + T - 1) / T;       // warp per node
    int bW4 = (NN / 4 * 32 + T - 1) / T;  // warp per 4 nodes
    int bM = (NN + 127) / 128;            // mma tiles
    int bF = (GG * OUTF + T - 1) / T;

    k_prep<<<bN, T>>>(W2);
    k_fill<<<bE, T>>>(src, dst);
    k_gemm_in<<<bW4, T>>>(x, W1);
    k_agg1<<<bW, T>>>(b1);
    k_gemm2_mma<<<bM, T, SMEM_MMA>>>();
    k_agg_pool<<<bW, T>>>(b2, batch);
    k_final<<<bF, T>>>(Wl, bl, out);
}

// round 9
// speedup vs baseline: 1.9195x; 1.0961x over previous
#include <cuda_runtime.h>
#include <cuda_fp16.h>

#define NN   100000
#define EE   1600000
#define GG   100
#define HH   128
#define OUTF 10
#define CAP  128
#define PITCH 136   // smem row pitch in halves (272B: conflict-free for ldmatrix)

typedef unsigned long long u64;

// ---------- device scratch ----------
__device__ __half g_bufA[(size_t)NN * HH];   // hs0 = dis*(x@W1), fp16
__device__ __half g_bufCh[(size_t)NN * HH];  // h1 = relu(agg1), fp16
__device__ __half g_bufB[(size_t)NN * HH];   // zs = dis*(h1@W2), fp16
__device__ __half g_W2h[HH * HH];            // W2 in fp16
__device__ int    g_pad[(size_t)NN * CAP];   // scaled src indices (src*32)
__device__ int    g_cur[NN];
__device__ float  g_dis[NN];
__device__ float  g_pooled[GG * HH];
__device__ float  g_gcnt[GG];

__device__ __forceinline__ unsigned smem_u32(const void* p) {
    return (unsigned)__cvta_generic_to_shared(p);
}

__device__ __forceinline__ uint2 pack_h4(float4 o) {
    __half2 lo = __floats2half2_rn(o.x, o.y);
    __half2 hi = __floats2half2_rn(o.z, o.w);
    uint2 r;
    r.x = *(unsigned*)&lo;
    r.y = *(unsigned*)&hi;
    return r;
}

// ---------- mma / ldmatrix ----------
__device__ __forceinline__ void mma16816(float d[4], const unsigned a[4],
                                         const unsigned b[2], const float c[4]) {
    asm volatile(
        "mma.sync.aligned.m16n8k16.row.col.f32.f16.f16.f32 "
        "{%0,%1,%2,%3}, {%4,%5,%6,%7}, {%8,%9}, {%10,%11,%12,%13};\n"
        : "=f"(d[0]), "=f"(d[1]), "=f"(d[2]), "=f"(d[3])
        : "r"(a[0]), "r"(a[1]), "r"(a[2]), "r"(a[3]),
          "r"(b[0]), "r"(b[1]),
          "f"(c[0]), "f"(c[1]), "f"(c[2]), "f"(c[3]));
}
__device__ __forceinline__ void ldsm_x4(unsigned r[4], unsigned addr) {
    asm volatile("ldmatrix.sync.aligned.m8n8.x4.shared.b16 {%0,%1,%2,%3}, [%4];\n"
        : "=r"(r[0]), "=r"(r[1]), "=r"(r[2]), "=r"(r[3]) : "r"(addr));
}
__device__ __forceinline__ void ldsm_x2_t(unsigned r[2], unsigned addr) {
    asm volatile("ldmatrix.sync.aligned.m8n8.x2.trans.shared.b16 {%0,%1}, [%2];\n"
        : "=r"(r[0]), "=r"(r[1]) : "r"(addr));
}

// ---------- gather: full warp, lane owns 4 features (uint2), fp16 acc ----------
__device__ __forceinline__ void hacc2(__half2& h0, __half2& h1, uint2 v) {
    h0 = __hadd2(h0, *(__half2*)&v.x);
    h1 = __hadd2(h1, *(__half2*)&v.y);
}

__device__ __forceinline__ float4 gather_sum_h(const __half* __restrict__ buf,
                                               int n, int lane) {
    int cnt = g_cur[n]; if (cnt > CAP) cnt = CAP;
    const int* lst = g_pad + (size_t)n * CAP;
    const uint2* A = (const uint2*)buf;           // row = 32 uint2
    float4 fa = {0.f, 0.f, 0.f, 0.f};
    const __half2 z = __float2half2_rn(0.f);
    __half2 h0 = z, h1 = z;

    int k = 0, sf = 0;
    for (; k + 8 <= cnt; k += 8) {
        int4 a = *(const int4*)&lst[k];
        int4 b = *(const int4*)&lst[k + 4];
        uint2 v0 = __ldg(&A[a.x + lane]);
        uint2 v1 = __ldg(&A[a.y + lane]);
        uint2 v2 = __ldg(&A[a.z + lane]);
        uint2 v3 = __ldg(&A[a.w + lane]);
        uint2 v4 = __ldg(&A[b.x + lane]);
        uint2 v5 = __ldg(&A[b.y + lane]);
        uint2 v6 = __ldg(&A[b.z + lane]);
        uint2 v7 = __ldg(&A[b.w + lane]);
        hacc2(h0, h1, v0); hacc2(h0, h1, v1);
        hacc2(h0, h1, v2); hacc2(h0, h1, v3);
        hacc2(h0, h1, v4); hacc2(h0, h1, v5);
        hacc2(h0, h1, v6); hacc2(h0, h1, v7);
        if (++sf == 2) {                          // flush every 16 edges
            float2 f0 = __half22float2(h0), f1 = __half22float2(h1);
            fa.x += f0.x; fa.y += f0.y; fa.z += f1.x; fa.w += f1.y;
            h0 = z; h1 = z; sf = 0;
        }
    }
    if (k + 4 <= cnt) {                           // 4-edge batch (shortens tail)
        int4 a = *(const int4*)&lst[k];
        uint2 v0 = __ldg(&A[a.x + lane]);
        uint2 v1 = __ldg(&A[a.y + lane]);
        uint2 v2 = __ldg(&A[a.z + lane]);
        uint2 v3 = __ldg(&A[a.w + lane]);
        hacc2(h0, h1, v0); hacc2(h0, h1, v1);
        hacc2(h0, h1, v2); hacc2(h0, h1, v3);
        k += 4;
    }
    for (; k < cnt; k++)
        hacc2(h0, h1, __ldg(&A[__ldg(&lst[k]) + lane]));
    hacc2(h0, h1, A[n * 32 + lane]);              // self loop
    float2 f0 = __half22float2(h0), f1 = __half22float2(h1);
    fa.x += f0.x; fa.y += f0.y; fa.z += f1.x; fa.w += f1.y;
    return fa;
}

// ---------- kernels ----------
__global__ void k_prep(const float* __restrict__ W2) {
    int i = blockIdx.x * blockDim.x + threadIdx.x;
    if (i < NN) g_cur[i] = 0;
    if (i < GG * HH) g_pooled[i] = 0.f;
    if (i < GG) g_gcnt[i] = 0.f;
    if (i < HH * HH) g_W2h[i] = __float2half_rn(W2[i]);
}

__global__ void k_fill(const int* __restrict__ src, const int* __restrict__ dst) {
    int i = blockIdx.x * blockDim.x + threadIdx.x;
    if (i >= EE / 4) return;
    int4 d4 = __ldg(&((const int4*)dst)[i]);
    int4 s4 = __ldg(&((const int4*)src)[i]);
    int p0 = atomicAdd(&g_cur[d4.x], 1); if (p0 < CAP) g_pad[d4.x * CAP + p0] = s4.x * 32;
    int p1 = atomicAdd(&g_cur[d4.y], 1); if (p1 < CAP) g_pad[d4.y * CAP + p1] = s4.y * 32;
    int p2 = atomicAdd(&g_cur[d4.z], 1); if (p2 < CAP) g_pad[d4.z * CAP + p2] = s4.z * 32;
    int p3 = atomicAdd(&g_cur[d4.w], 1); if (p3 < CAP) g_pad[d4.w * CAP + p3] = s4.w * 32;
}

// hs0 = dis_n * (x_n @ W1) -> fp16; publishes g_dis. Warp per 4 nodes.
__global__ void __launch_bounds__(256) k_gemm_in(const float* __restrict__ x,
                                                 const float* __restrict__ W1) {
    int gid = blockIdx.x * blockDim.x + threadIdx.x;
    int w = gid >> 5, lane = gid & 31;
    int n0 = w * 4;
    if (n0 >= NN) return;
    const float4* W = ((const float4*)W1) + lane;
    float4 w0 = W[0], w1 = W[32], w2 = W[64];
#pragma unroll
    for (int p = 0; p < 4; p++) {
        int n = n0 + p;
        float dis = rsqrtf((float)(g_cur[n] + 1));
        if (lane == 0) g_dis[n] = dis;
        float x0 = __ldg(&x[n * 3 + 0]);
        float x1 = __ldg(&x[n * 3 + 1]);
        float x2 = __ldg(&x[n * 3 + 2]);
        float4 o;
        o.x = dis * fmaf(x0, w0.x, fmaf(x1, w1.x, x2 * w2.x));
        o.y = dis * fmaf(x0, w0.y, fmaf(x1, w1.y, x2 * w2.y));
        o.z = dis * fmaf(x0, w0.z, fmaf(x1, w1.z, x2 * w2.z));
        o.w = dis * fmaf(x0, w0.w, fmaf(x1, w1.w, x2 * w2.w));
        ((uint2*)(g_bufA + (size_t)n * HH))[lane] = pack_h4(o);
    }
}

// Layer-1 aggregate + bias + relu -> h1 (fp16). Warp per node.
__global__ void __launch_bounds__(256) k_agg1(const float* __restrict__ b1) {
    int gid = blockIdx.x * blockDim.x + threadIdx.x;
    int n = gid >> 5, lane = gid & 31;
    if (n >= NN) return;
    float4 a = gather_sum_h(g_bufA, n, lane);
    float dis = g_dis[n];
    float4 b = ((const float4*)b1)[lane];
    float4 o;
    o.x = fmaxf(fmaf(a.x, dis, b.x), 0.f);
    o.y = fmaxf(fmaf(a.y, dis, b.y), 0.f);
    o.z = fmaxf(fmaf(a.z, dis, b.z), 0.f);
    o.w = fmaxf(fmaf(a.w, dis, b.w), 0.f);
    ((uint2*)(g_bufCh + (size_t)n * HH))[lane] = pack_h4(o);
}

// zs = dis * (h1 @ W2) -> fp16, via HMMA m16n8k16.
__global__ void __launch_bounds__(256) k_gemm2_mma() {
    extern __shared__ __half sh[];
    __half* sh_h = sh;                  // [128][PITCH]
    __half* sh_w = sh + 128 * PITCH;    // [128][PITCH]
    int t = threadIdx.x;
    int nb0 = blockIdx.x * 128;

    for (int i = t; i < 128 * 16; i += 256) {
        int r = i >> 4, c8 = (i & 15) * 8;
        int node = nb0 + r; if (node >= NN) node = NN - 1;
        *(uint4*)&sh_h[r * PITCH + c8] = *(const uint4*)&g_bufCh[(size_t)node * HH + c8];
        *(uint4*)&sh_w[r * PITCH + c8] = *(const uint4*)&g_W2h[r * HH + c8];
    }
    __syncthreads();

    int w = t >> 5, lane = t & 31;
    int r0 = w * 16;

    float acc[16][4];
#pragma unroll
    for (int j = 0; j < 16; j++)
#pragma unroll
        for (int q = 0; q < 4; q++) acc[j][q] = 0.f;

    int a_row = r0 + (lane & 15);
    int a_col = (lane >> 4) * 8;
    int b_lane = lane & 15;

    for (int kc = 0; kc < 8; kc++) {
        int k0 = kc * 16;
        unsigned a[4];
        ldsm_x4(a, smem_u32(&sh_h[a_row * PITCH + k0 + a_col]));
        unsigned b_base = smem_u32(&sh_w[(k0 + b_lane) * PITCH]);
#pragma unroll
        for (int j = 0; j < 16; j++) {
            unsigned b[2];
            ldsm_x2_t(b, b_base + j * 8 * sizeof(__half));
            mma16816(acc[j], a, b, acc[j]);
        }
    }

    int lrow = lane >> 2;
    int lcol = (lane & 3) * 2;
    int node0 = nb0 + r0 + lrow;
    int node1 = node0 + 8;
    float dis0 = (node0 < NN) ? g_dis[node0] : 0.f;
    float dis1 = (node1 < NN) ? g_dis[node1] : 0.f;
#pragma unroll
    for (int j = 0; j < 16; j++) {
        if (node0 < NN) {
            __half2 p = __floats2half2_rn(acc[j][0] * dis0, acc[j][1] * dis0);
            *(__half2*)&g_bufB[(size_t)node0 * HH + j * 8 + lcol] = p;
        }
        if (node1 < NN) {
            __half2 p = __floats2half2_rn(acc[j][2] * dis1, acc[j][3] * dis1);
            *(__half2*)&g_bufB[(size_t)node1 * HH + j * 8 + lcol] = p;
        }
    }
}

// Layer-2 aggregate + relu + mean-pool. Atomic-free staging + tree reduction.
// Grid is exactly NN/8 blocks of 8 warps -> every warp has a valid node.
__global__ void __launch_bounds__(256) k_agg_pool(const float* __restrict__ b2,
                                                   const int* __restrict__ batch) {
    __shared__ float stage[8][HH];
    __shared__ int wg[8];
    int tid = threadIdx.x;
    int w = tid >> 5, lane = tid & 31;
    int n = blockIdx.x * 8 + w;

    float4 a = gather_sum_h(g_bufB, n, lane);
    float dis = g_dis[n];
    float4 b = ((const float4*)b2)[lane];
    float4 o;
    o.x = fmaxf(fmaf(a.x, dis, b.x), 0.f);
    o.y = fmaxf(fmaf(a.y, dis, b.y), 0.f);
    o.z = fmaxf(fmaf(a.z, dis, b.z), 0.f);
    o.w = fmaxf(fmaf(a.w, dis, b.w), 0.f);
    ((float4*)stage[w])[lane] = o;
    if (lane == 0) wg[w] = batch[n];
    __syncthreads();

    if (tid < HH) {
        int g0 = wg[0];
        float s = 0.f;
#pragma unroll
        for (int ww = 0; ww < 8; ww++) {
            float v = stage[ww][tid];
            if (wg[ww] == g0) s += v;
            else atomicAdd(&g_pooled[wg[ww] * HH + tid], v);   // rare boundary
        }
        atomicAdd(&g_pooled[g0 * HH + tid], s);
    } else if (tid == HH) {
        int g0 = wg[0];
        float c0 = 0.f;
#pragma unroll
        for (int ww = 0; ww < 8; ww++) {
            if (wg[ww] == g0) c0 += 1.f;
            else atomicAdd(&g_gcnt[wg[ww]], 1.f);
        }
        atomicAdd(&g_gcnt[g0], c0);
    }
}

__global__ void k_final(const float* __restrict__ Wl, const float* __restrict__ bl,
                        float* __restrict__ out) {
    int idx = blockIdx.x * blockDim.x + threadIdx.x;
    if (idx >= GG * OUTF) return;
    int g = idx / OUTF, o = idx % OUTF;
    float inv = 1.f / fmaxf(g_gcnt[g], 1.f);
    float s = 0.f;
#pragma unroll 8
    for (int k = 0; k < HH; k++)
        s = fmaf(g_pooled[g * HH + k], Wl[k * OUTF + o], s);
    out[idx] = fmaf(s, inv, bl[o]);
}

// ---------- launch ----------
extern "C" void kernel_launch(void* const* d_in, const int* in_sizes, int n_in,
                              void* d_out, int out_size) {
    const float* x     = (const float*)d_in[0];
    const int*   ei    = (const int*)d_in[1];
    const int*   src   = ei;
    const int*   dst   = ei + EE;
    const int*   batch = (const int*)d_in[2];
    const float* W1    = (const float*)d_in[3];
    const float* b1    = (const float*)d_in[4];
    const float* W2    = (const float*)d_in[5];
    const float* b2    = (const float*)d_in[6];
    const float* Wl    = (const float*)d_in[7];
    const float* bl    = (const float*)d_in[8];
    float* out = (float*)d_out;

    const int SMEM_MMA = 2 * 128 * PITCH * (int)sizeof(__half);   // 69632
    cudaFuncSetAttribute(k_gemm2_mma,
                         cudaFuncAttributeMaxDynamicSharedMemorySize, SMEM_MMA);

    const int T = 256;
    int bN = (NN + T - 1) / T;
    int bE = (EE / 4 + T - 1) / T;
    int bW = (NN * 32 + T - 1) / T;       // 12500: warp per node (exact)
    int bW4 = (NN / 4 * 32 + T - 1) / T;  // warp per 4 nodes
    int bM = (NN + 127) / 128;            // mma tiles
    int bF = (GG * OUTF + T - 1) / T;

    k_prep<<<bN, T>>>(W2);
    k_fill<<<bE, T>>>(src, dst);
    k_gemm_in<<<bW4, T>>>(x, W1);
    k_agg1<<<bW, T>>>(b1);
    k_gemm2_mma<<<bM, T, SMEM_MMA>>>();
    k_agg_pool<<<bW, T>>>(b2, batch);
    k_final<<<bF, T>>>(Wl, bl, out);
}

// round 10
// speedup vs baseline: 2.4020x; 1.2514x over previous
#include <cuda_runtime.h>
#include <cuda_fp16.h>

#define NN   100000
#define EE   1600000
#define GG   100
#define HH   128
#define OUTF 10
#define CAP  128
#define PITCH 136   // smem row pitch in halves (conflict-free for ldmatrix)

// ---------- device scratch (static zero-init; self-cleaning across replays) ----------
__device__ __half g_hs1[(size_t)NN * HH];  // dis * relu(layer1)  (pre-scaled msgs)
__device__ __half g_ts[(size_t)NN * HH];   // dis * T  (gemm2 input)
__device__ int    g_pad[(size_t)NN * CAP]; // scaled src indices (src*32)
__device__ int    g_cur[NN];               // in-degree / cursor (zeroed by k_agg2)
__device__ float4 g_xs[NN];                // (dis*x0, dis*x1, dis*x2, dis)
__device__ float  g_dis[NN];
__device__ float  g_pooled[GG * HH];       // zeroed by k_final
__device__ float  g_gcnt[GG];              // zeroed by k_final

__device__ __forceinline__ unsigned smem_u32(const void* p) {
    return (unsigned)__cvta_generic_to_shared(p);
}
__device__ __forceinline__ uint2 pack_h4(float4 o) {
    __half2 lo = __floats2half2_rn(o.x, o.y);
    __half2 hi = __floats2half2_rn(o.z, o.w);
    uint2 r; r.x = *(unsigned*)&lo; r.y = *(unsigned*)&hi; return r;
}

// ---------- mma / ldmatrix ----------
__device__ __forceinline__ void mma16816(float d[4], const unsigned a[4],
                                         const unsigned b[2], const float c[4]) {
    asm volatile(
        "mma.sync.aligned.m16n8k16.row.col.f32.f16.f16.f32 "
        "{%0,%1,%2,%3}, {%4,%5,%6,%7}, {%8,%9}, {%10,%11,%12,%13};\n"
        : "=f"(d[0]), "=f"(d[1]), "=f"(d[2]), "=f"(d[3])
        : "r"(a[0]), "r"(a[1]), "r"(a[2]), "r"(a[3]),
          "r"(b[0]), "r"(b[1]),
          "f"(c[0]), "f"(c[1]), "f"(c[2]), "f"(c[3]));
}
__device__ __forceinline__ void ldsm_x4(unsigned r[4], unsigned addr) {
    asm volatile("ldmatrix.sync.aligned.m8n8.x4.shared.b16 {%0,%1,%2,%3}, [%4];\n"
        : "=r"(r[0]), "=r"(r[1]), "=r"(r[2]), "=r"(r[3]) : "r"(addr));
}
__device__ __forceinline__ void ldsm_x2_t(unsigned r[2], unsigned addr) {
    asm volatile("ldmatrix.sync.aligned.m8n8.x2.trans.shared.b16 {%0,%1}, [%2];\n"
        : "=r"(r[0]), "=r"(r[1]) : "r"(addr));
}

// ---------- fp16 feature-space gather (lane owns 4 features = uint2) ----------
__device__ __forceinline__ void hacc2(__half2& h0, __half2& h1, uint2 v) {
    h0 = __hadd2(h0, *(__half2*)&v.x);
    h1 = __hadd2(h1, *(__half2*)&v.y);
}

__device__ __forceinline__ float4 gather_sum_h(const __half* __restrict__ buf,
                                               int n, int lane) {
    int cnt = g_cur[n]; if (cnt > CAP) cnt = CAP;
    const int* lst = g_pad + (size_t)n * CAP;
    const uint2* A = (const uint2*)buf;           // row = 32 uint2
    float4 fa = {0.f, 0.f, 0.f, 0.f};
    const __half2 z = __float2half2_rn(0.f);
    __half2 h0 = z, h1 = z;

    int k = 0, sf = 0;
    for (; k + 8 <= cnt; k += 8) {
        int4 a = *(const int4*)&lst[k];
        int4 b = *(const int4*)&lst[k + 4];
        uint2 v0 = __ldg(&A[a.x + lane]);
        uint2 v1 = __ldg(&A[a.y + lane]);
        uint2 v2 = __ldg(&A[a.z + lane]);
        uint2 v3 = __ldg(&A[a.w + lane]);
        uint2 v4 = __ldg(&A[b.x + lane]);
        uint2 v5 = __ldg(&A[b.y + lane]);
        uint2 v6 = __ldg(&A[b.z + lane]);
        uint2 v7 = __ldg(&A[b.w + lane]);
        hacc2(h0, h1, v0); hacc2(h0, h1, v1);
        hacc2(h0, h1, v2); hacc2(h0, h1, v3);
        hacc2(h0, h1, v4); hacc2(h0, h1, v5);
        hacc2(h0, h1, v6); hacc2(h0, h1, v7);
        if (++sf == 2) {                          // flush every 16 edges
            float2 f0 = __half22float2(h0), f1 = __half22float2(h1);
            fa.x += f0.x; fa.y += f0.y; fa.z += f1.x; fa.w += f1.y;
            h0 = z; h1 = z; sf = 0;
        }
    }
    if (k + 4 <= cnt) {
        int4 a = *(const int4*)&lst[k];
        uint2 v0 = __ldg(&A[a.x + lane]);
        uint2 v1 = __ldg(&A[a.y + lane]);
        uint2 v2 = __ldg(&A[a.z + lane]);
        uint2 v3 = __ldg(&A[a.w + lane]);
        hacc2(h0, h1, v0); hacc2(h0, h1, v1);
        hacc2(h0, h1, v2); hacc2(h0, h1, v3);
        k += 4;
    }
    for (; k < cnt; k++)
        hacc2(h0, h1, __ldg(&A[__ldg(&lst[k]) + lane]));
    hacc2(h0, h1, A[n * 32 + lane]);              // self loop (pre-scaled row)
    float2 f0 = __half22float2(h0), f1 = __half22float2(h1);
    fa.x += f0.x; fa.y += f0.y; fa.z += f1.x; fa.w += f1.y;
    return fa;
}

// ---------- kernels ----------
// build padded adjacency; g_cur starts zero (static init / zeroed by k_agg2)
__global__ void k_fill(const int* __restrict__ src, const int* __restrict__ dst) {
    int i = blockIdx.x * blockDim.x + threadIdx.x;
    if (i >= EE / 4) return;
    int4 d4 = __ldg(&((const int4*)dst)[i]);
    int4 s4 = __ldg(&((const int4*)src)[i]);
    int p0 = atomicAdd(&g_cur[d4.x], 1); if (p0 < CAP) g_pad[d4.x * CAP + p0] = s4.x * 32;
    int p1 = atomicAdd(&g_cur[d4.y], 1); if (p1 < CAP) g_pad[d4.y * CAP + p1] = s4.y * 32;
    int p2 = atomicAdd(&g_cur[d4.z], 1); if (p2 < CAP) g_pad[d4.z * CAP + p2] = s4.z * 32;
    int p3 = atomicAdd(&g_cur[d4.w], 1); if (p3 < CAP) g_pad[d4.w * CAP + p3] = s4.w * 32;
}

// dis + pre-scaled x
__global__ void k_pre(const float* __restrict__ x) {
    int i = blockIdx.x * blockDim.x + threadIdx.x;
    if (i >= NN) return;
    float dis = rsqrtf((float)(g_cur[i] + 1));
    g_dis[i] = dis;
    float x0 = __ldg(&x[i * 3 + 0]);
    float x1 = __ldg(&x[i * 3 + 1]);
    float x2 = __ldg(&x[i * 3 + 2]);
    g_xs[i] = make_float4(dis * x0, dis * x1, dis * x2, dis);
}

// Layer 1 fused: x-space gather (thread per node) + W1 gemm (warp per node group)
// hs1 = dis * relu( dis*(S @ W1) + b1 ),  S = xs[n] + sum_j xs[j]
__global__ void __launch_bounds__(256) k_layer1(const float* __restrict__ W1,
                                                const float* __restrict__ b1) {
    __shared__ float4 sS[256];
    int tid = threadIdx.x;
    int n = blockIdx.x * 256 + tid;

    if (n < NN) {
        int cnt = g_cur[n]; if (cnt > CAP) cnt = CAP;
        const int* lst = g_pad + (size_t)n * CAP;
        float4 self = g_xs[n];
        float dis = self.w;
        float sx = self.x, sy = self.y, sz = self.z;
        int k = 0;
        for (; k + 4 <= cnt; k += 4) {
            int4 a = *(const int4*)&lst[k];
            float4 v0 = __ldg(&g_xs[a.x >> 5]);
            float4 v1 = __ldg(&g_xs[a.y >> 5]);
            float4 v2 = __ldg(&g_xs[a.z >> 5]);
            float4 v3 = __ldg(&g_xs[a.w >> 5]);
            sx += v0.x + v1.x + v2.x + v3.x;
            sy += v0.y + v1.y + v2.y + v3.y;
            sz += v0.z + v1.z + v2.z + v3.z;
        }
        for (; k < cnt; k++) {
            float4 v = __ldg(&g_xs[__ldg(&lst[k]) >> 5]);
            sx += v.x; sy += v.y; sz += v.z;
        }
        sS[tid] = make_float4(sx, sy, sz, dis);
    }
    __syncthreads();

    int w = tid >> 5, lane = tid & 31;
    const float4* W = ((const float4*)W1) + lane;
    float4 w0 = W[0], w1 = W[32], w2 = W[64];
    float4 bb = ((const float4*)b1)[lane];
    int base = blockIdx.x * 256 + w * 32;
#pragma unroll 4
    for (int it = 0; it < 32; it++) {
        int node = base + it;
        if (node >= NN) break;
        float4 s = sS[w * 32 + it];        // broadcast LDS
        float dis = s.w;
        float4 o;
        float tx = fmaf(dis, fmaf(s.x, w0.x, fmaf(s.y, w1.x, s.z * w2.x)), bb.x);
        float ty = fmaf(dis, fmaf(s.x, w0.y, fmaf(s.y, w1.y, s.z * w2.y)), bb.y);
        float tz = fmaf(dis, fmaf(s.x, w0.z, fmaf(s.y, w1.z, s.z * w2.z)), bb.z);
        float tw = fmaf(dis, fmaf(s.x, w0.w, fmaf(s.y, w1.w, s.z * w2.w)), bb.w);
        o.x = fmaxf(tx, 0.f) * dis;
        o.y = fmaxf(ty, 0.f) * dis;
        o.z = fmaxf(tz, 0.f) * dis;
        o.w = fmaxf(tw, 0.f) * dis;
        ((uint2*)(g_hs1 + (size_t)node * HH))[lane] = pack_h4(o);
    }
}

// Layer-2 gather: ts = dis_i * (hs1_i + sum_j hs1_j). Warp per node.
// Also resets g_cur for the next replay (last reader of g_cur).
__global__ void __launch_bounds__(256) k_agg2() {
    int gid = blockIdx.x * blockDim.x + threadIdx.x;
    int n = gid >> 5, lane = gid & 31;
    float4 a = gather_sum_h(g_hs1, n, lane);
    if (lane == 0) g_cur[n] = 0;               // self-clean for next launch
    float dis = g_dis[n];
    float4 o;
    o.x = a.x * dis; o.y = a.y * dis; o.z = a.z * dis; o.w = a.w * dis;
    ((uint2*)(g_ts + (size_t)n * HH))[lane] = pack_h4(o);
}

// HMMA ts@W2 + bias + relu + mean-pool, all in one kernel.
__global__ void __launch_bounds__(256) k_gemm2pool(const float* __restrict__ W2,
                                                   const float* __restrict__ b2,
                                                   const int* __restrict__ batch) {
    extern __shared__ __half sh[];
    __half* sh_h = sh;                  // [128][PITCH]
    __half* sh_w = sh + 128 * PITCH;    // [128][PITCH]
    __shared__ float sb2[HH];
    __shared__ int sbatch[128];
    int t = threadIdx.x;
    int nb0 = blockIdx.x * 128;

    // stage ts tile + W2 (fp32 -> fp16 on the fly)
    const float4* W2f4 = (const float4*)W2;
    for (int i = t; i < 128 * 16; i += 256) {
        int r = i >> 4, c8 = (i & 15) * 8;
        int node = nb0 + r; if (node >= NN) node = NN - 1;
        *(uint4*)&sh_h[r * PITCH + c8] = *(const uint4*)&g_ts[(size_t)node * HH + c8];
        float4 wa = __ldg(&W2f4[(r * HH + c8) >> 2]);
        float4 wb = __ldg(&W2f4[((r * HH + c8) >> 2) + 1]);
        uint4 pw;
        __half2 p0 = __floats2half2_rn(wa.x, wa.y);
        __half2 p1 = __floats2half2_rn(wa.z, wa.w);
        __half2 p2 = __floats2half2_rn(wb.x, wb.y);
        __half2 p3 = __floats2half2_rn(wb.z, wb.w);
        pw.x = *(unsigned*)&p0; pw.y = *(unsigned*)&p1;
        pw.z = *(unsigned*)&p2; pw.w = *(unsigned*)&p3;
        *(uint4*)&sh_w[r * PITCH + c8] = pw;
    }
    if (t < HH) sb2[t] = b2[t];
    if (t < 128) {
        int node = nb0 + t;
        sbatch[t] = (node < NN) ? __ldg(&batch[node]) : -1;
    }
    __syncthreads();

    int w = t >> 5, lane = t & 31;
    int r0 = w * 16;
    float acc[16][4];
#pragma unroll
    for (int j = 0; j < 16; j++)
#pragma unroll
        for (int q = 0; q < 4; q++) acc[j][q] = 0.f;

    int a_row = r0 + (lane & 15);
    int a_col = (lane >> 4) * 8;
    int b_lane = lane & 15;

    for (int kc = 0; kc < 8; kc++) {
        int k0 = kc * 16;
        unsigned a[4];
        ldsm_x4(a, smem_u32(&sh_h[a_row * PITCH + k0 + a_col]));
        unsigned b_base = smem_u32(&sh_w[(k0 + b_lane) * PITCH]);
#pragma unroll
        for (int j = 0; j < 16; j++) {
            unsigned b[2];
            ldsm_x2_t(b, b_base + j * 8 * sizeof(__half));
            mma16816(acc[j], a, b, acc[j]);
        }
    }
    __syncthreads();                    // done with sh_h/sh_w -> reuse as staging

    float* stg = (float*)sh;            // [128][128] fp32 = 64KB (fits region)
    int lrow = lane >> 2;
    int lcol = (lane & 3) * 2;
    int row0 = r0 + lrow, row1 = row0 + 8;
#pragma unroll
    for (int j = 0; j < 16; j++) {
        int col = j * 8 + lcol;
        stg[row0 * 128 + col]     = fmaxf(acc[j][0] + sb2[col], 0.f);
        stg[row0 * 128 + col + 1] = fmaxf(acc[j][1] + sb2[col + 1], 0.f);
        stg[row1 * 128 + col]     = fmaxf(acc[j][2] + sb2[col], 0.f);
        stg[row1 * 128 + col + 1] = fmaxf(acc[j][3] + sb2[col + 1], 0.f);
    }
    __syncthreads();

    // pool: thread f (0..127) reduces column f over the tile's rows by graph id
    if (t < HH) {
        int g0 = sbatch[0];
        float s = 0.f;
        for (int r = 0; r < 128; r++) {
            int g = sbatch[r];
            if (g < 0) continue;
            float v = stg[r * 128 + t];
            if (g == g0) s += v;
            else atomicAdd(&g_pooled[g * HH + t], v);   // rare boundary rows
        }
        atomicAdd(&g_pooled[g0 * HH + t], s);
    } else if (t == HH) {
        int g0 = sbatch[0];
        float c0 = 0.f;
        for (int r = 0; r < 128; r++) {
            int g = sbatch[r];
            if (g < 0) continue;
            if (g == g0) c0 += 1.f;
            else atomicAdd(&g_gcnt[g], 1.f);
        }
        atomicAdd(&g_gcnt[g0], c0);
    }
}

// final head (single block) + zero pooled state for next replay
__global__ void __launch_bounds__(1024) k_final(const float* __restrict__ Wl,
                                                const float* __restrict__ bl,
                                                float* __restrict__ out) {
    int idx = threadIdx.x;
    if (idx < GG * OUTF) {
        int g = idx / OUTF, o = idx % OUTF;
        float inv = 1.f / fmaxf(g_gcnt[g], 1.f);
        float s = 0.f;
#pragma unroll 8
        for (int k = 0; k < HH; k++)
            s = fmaf(g_pooled[g * HH + k], Wl[k * OUTF + o], s);
        out[idx] = fmaf(s, inv, bl[o]);
    }
    __syncthreads();
    for (int i = idx; i < GG * HH; i += 1024) g_pooled[i] = 0.f;
    if (idx < GG) g_gcnt[idx] = 0.f;
}

// ---------- launch ----------
extern "C" void kernel_launch(void* const* d_in, const int* in_sizes, int n_in,
                              void* d_out, int out_size) {
    const float* x     = (const float*)d_in[0];
    const int*   ei    = (const int*)d_in[1];
    const int*   src   = ei;
    const int*   dst   = ei + EE;
    const int*   batch = (const int*)d_in[2];
    const float* W1    = (const float*)d_in[3];
    const float* b1    = (const float*)d_in[4];
    const float* W2    = (const float*)d_in[5];
    const float* b2    = (const float*)d_in[6];
    const float* Wl    = (const float*)d_in[7];
    const float* bl    = (const float*)d_in[8];
    float* out = (float*)d_out;

    const int SMEM_MMA = 2 * 128 * PITCH * (int)sizeof(__half);   // 69632
    cudaFuncSetAttribute(k_gemm2pool,
                         cudaFuncAttributeMaxDynamicSharedMemorySize, SMEM_MMA);

    const int T = 256;
    int bE  = (EE / 4 + T - 1) / T;
    int bN  = (NN + T - 1) / T;         // 391
    int bW  = (NN * 32 + T - 1) / T;    // 12500 (warp per node, exact)
    int bM  = (NN + 127) / 128;         // 782 mma tiles

    k_fill<<<bE, T>>>(src, dst);
    k_pre<<<bN, T>>>(x);
    k_layer1<<<bN, T>>>(W1, b1);
    k_agg2<<<bW, T>>>();
    k_gemm2pool<<<bM, T, SMEM_MMA>>>(W2, b2, batch);
    k_final<<<1, 1024>>>(Wl, bl, out);
}